// round 5
// baseline (speedup 1.0000x reference)
#include <cuda_runtime.h>
#include <math.h>
#include <stdint.h>

#define Bb 256
#define Ll 200
#define Hh 768
#define Dd 64
#define Mm (Bb*Ll)          // 51200
#define G6 384
#define NS 6

#define OFF_PROBS 0
#define OFF_TTE   1536
#define OFF_CI    1792
#define OFF_HIST  3328

// ---------------- scratch (device globals; no allocation) ----------------
__device__ __align__(16) float g_gates[6][(size_t)Mm*Dd];
__device__ __align__(16) float g_h[(size_t)Mm*Dd];
__device__ __align__(16) float g_clast[Bb*Dd];
__device__ __align__(16) float g_gcur[4][Bb*Dd];
__device__ __align__(16) float g_hcur[Bb*Dd];
__device__ __align__(16) float g_tdirT[(size_t)G6*Bb];   // [col][b]
__device__ __align__(16) float g_v[G6];
__device__ __align__(16) float g_beff[G6];               // bg + btime@WgT + be@WgE
__device__ __align__(16) float g_Wc[(size_t)Hh*G6];      // We @ Wg[0:64,:]

// ---------------- math helpers ----------------
__device__ __forceinline__ float sigm_(float x){ return 1.f/(1.f+expf(-x)); }
__device__ __forceinline__ float softplus_(float x){
    return (x > 0.f) ? (x + log1pf(expf(-x))) : log1pf(expf(x));
}
__device__ __forceinline__ float gelu_(float x){
    return 0.5f * x * (1.f + erff(x * 0.70710678118654752440f));
}
__device__ __forceinline__ float act_(float g, int ch, float dt){
    if (ch == 2) return tanhf(g);
    if (ch == 4) return expf(-softplus_(g) * dt);
    if (ch == 5) return g;
    return sigm_(g);
}

// ---------------- tf32 helpers ----------------
__device__ __forceinline__ uint32_t tf32_(float x){
    uint32_t r; asm("cvt.rna.tf32.f32 %0, %1;" : "=r"(r) : "f"(x)); return r;
}
__device__ __forceinline__ void split_sts(uint32_t* ph, uint32_t* pl, float4 v){
    uint32_t h0=tf32_(v.x), h1=tf32_(v.y), h2=tf32_(v.z), h3=tf32_(v.w);
    uint32_t l0=tf32_(v.x-__uint_as_float(h0));
    uint32_t l1=tf32_(v.y-__uint_as_float(h1));
    uint32_t l2=tf32_(v.z-__uint_as_float(h2));
    uint32_t l3=tf32_(v.w-__uint_as_float(h3));
    *(uint4*)ph = make_uint4(h0,h1,h2,h3);
    *(uint4*)pl = make_uint4(l0,l1,l2,l3);
}
__device__ __forceinline__ void mma_(float* c,
    uint32_t a0, uint32_t a1, uint32_t a2, uint32_t a3, uint32_t b0, uint32_t b1){
    asm volatile(
        "mma.sync.aligned.m16n8k8.row.col.f32.tf32.tf32.f32 "
        "{%0,%1,%2,%3}, {%4,%5,%6,%7}, {%8,%9}, {%0,%1,%2,%3};"
        : "+f"(c[0]), "+f"(c[1]), "+f"(c[2]), "+f"(c[3])
        : "r"(a0), "r"(a1), "r"(a2), "r"(a3), "r"(b0), "r"(b1));
}

// ---------------- K0: rank-1 folds (v, beff') ----------------
__global__ void prep_kernel(const float* __restrict__ Wtime, const float* __restrict__ btime,
                            const float* __restrict__ Wg, const float* __restrict__ bg,
                            const float* __restrict__ be)
{
    int j = threadIdx.x;
    if (j >= G6) return;
    float v = 0.f, bf = bg[j];
    #pragma unroll 8
    for (int d = 0; d < Dd; d++){
        float wt = Wg[(size_t)(Dd + d) * G6 + j];
        v  += Wtime[d] * wt;
        bf += btime[d] * wt;
        bf += be[d] * Wg[(size_t)d * G6 + j];
    }
    g_v[j] = v;
    g_beff[j] = bf;
}

// ---------------- K0b: Wc = We @ Wg[0:64,:]  (768x384) ----------------
__global__ void wc_kernel(const float* __restrict__ We, const float* __restrict__ Wg)
{
    __shared__ float sWe[Dd];
    int k = blockIdx.x;       // 0..767
    int j = threadIdx.x;      // 0..383
    if (j < Dd) sWe[j] = We[(size_t)k * Dd + j];
    __syncthreads();
    float s = 0.f;
    #pragma unroll 16
    for (int d = 0; d < Dd; d++) s = fmaf(sWe[d], Wg[(size_t)d * G6 + j], s);
    g_Wc[(size_t)k * G6 + j] = s;
}

// ---------------- K1: 3xTF32 tensor-core GEMM + gate epilogues ----------------
// blocks [0,1200):    g = Xev@Wc + days*v + beff  -> g_gates (fam 0)
// blocks [1200,1206): gelu(cls@Ws1 + bs1)         -> g_tdirT (fam 1)
// blocks [1206,1210): gcur = act(cls@Wc + beff)   -> g_gcur  (fam 2)
__global__ void __launch_bounds__(256, 2) mma3_kernel(
    const float* __restrict__ Xev, const float* __restrict__ cls,
    const float* __restrict__ days,
    const float* __restrict__ Ws1, const float* __restrict__ bs1)
{
    __shared__ uint32_t sAh[128*20], sAl[128*20];   // 2560 words each, stride 20
    __shared__ uint32_t sBh[16*136], sBl[16*136];   // 2176 words each, stride 136

    const int t = threadIdx.x, lane = t & 31, wid = t >> 5;
    const int gid = lane >> 2, tg = lane & 3;
    const int wR = wid >> 2, wC = wid & 3;      // 2 x 4 warps, warp tile 64x32
    const int bx = blockIdx.x;

    int fam, m0, n0;
    const float* A; const float* B;
    if (bx < 1200){ fam = 0; m0 = (bx/3)*128; n0 = (bx%3)*128; A = Xev; B = g_Wc; }
    else if (bx < 1206){ int i = bx-1200; fam = 1; m0 = (i%2)*128; n0 = (i/2)*128; A = cls; B = Ws1; }
    else { int i = bx-1206; fam = 2; m0 = (i&1)*128; n0 = (i>>1)*128; A = cls; B = g_Wc; }

    float acc[4][4][4];
    #pragma unroll
    for (int mi=0;mi<4;mi++)
        #pragma unroll
        for (int ni=0;ni<4;ni++)
            #pragma unroll
            for (int q=0;q<4;q++) acc[mi][ni][q] = 0.f;

    const float* Ap = A + (size_t)(m0 + (t>>2)) * Hh + (t&3)*4;
    const float* Bp = B + (size_t)(t>>5) * G6 + n0 + (t&31)*4;
    const int aw = (t>>2)*20 + (t&3)*4;
    const int bw = (t>>5)*136 + (t&31)*4;

    float4 fa0 = *(const float4*)(Ap);
    float4 fa1 = *(const float4*)(Ap + (size_t)64*Hh);
    float4 fb0 = *(const float4*)(Bp);
    float4 fb1 = *(const float4*)(Bp + (size_t)8*G6);

    for (int kc = 0; kc < 48; kc++){
        split_sts(sAh+aw,        sAl+aw,        fa0);
        split_sts(sAh+aw+64*20,  sAl+aw+64*20,  fa1);
        split_sts(sBh+bw,        sBl+bw,        fb0);
        split_sts(sBh+bw+8*136,  sBl+bw+8*136,  fb1);
        __syncthreads();

        if (kc < 47){
            const float* Ap2 = Ap + (kc+1)*16;
            const float* Bp2 = Bp + (size_t)(kc+1)*16*G6;
            fa0 = *(const float4*)(Ap2);
            fa1 = *(const float4*)(Ap2 + (size_t)64*Hh);
            fb0 = *(const float4*)(Bp2);
            fb1 = *(const float4*)(Bp2 + (size_t)8*G6);
        }

        #pragma unroll
        for (int ks = 0; ks < 2; ks++){
            const int k0 = ks*8;
            uint32_t bh[4][2], bl[4][2];
            #pragma unroll
            for (int ni = 0; ni < 4; ni++){
                int c = wC*32 + ni*8 + gid;
                bh[ni][0] = sBh[(k0+tg)*136 + c];   bh[ni][1] = sBh[(k0+tg+4)*136 + c];
                bl[ni][0] = sBl[(k0+tg)*136 + c];   bl[ni][1] = sBl[(k0+tg+4)*136 + c];
            }
            #pragma unroll
            for (int mi = 0; mi < 4; mi++){
                int r = (wR*64 + mi*16 + gid)*20 + k0 + tg;
                uint32_t ah0=sAh[r], ah1=sAh[r+8*20], ah2=sAh[r+4], ah3=sAh[r+8*20+4];
                uint32_t al0=sAl[r], al1=sAl[r+8*20], al2=sAl[r+4], al3=sAl[r+8*20+4];
                #pragma unroll
                for (int ni = 0; ni < 4; ni++){
                    mma_(acc[mi][ni], ah0,ah1,ah2,ah3, bh[ni][0], bh[ni][1]);
                    mma_(acc[mi][ni], ah0,ah1,ah2,ah3, bl[ni][0], bl[ni][1]);
                    mma_(acc[mi][ni], al0,al1,al2,al3, bh[ni][0], bh[ni][1]);
                }
            }
        }
        __syncthreads();
    }

    // -------- epilogues --------
    if (fam == 1){
        #pragma unroll
        for (int mi = 0; mi < 4; mi++){
            int r0 = m0 + wR*64 + mi*16 + gid, r1 = r0 + 8;
            #pragma unroll
            for (int ni = 0; ni < 4; ni++){
                int c0 = n0 + wC*32 + ni*8 + 2*tg, c1 = c0 + 1;
                g_tdirT[(size_t)c0*Bb + r0] = gelu_(acc[mi][ni][0] + bs1[c0]);
                g_tdirT[(size_t)c1*Bb + r0] = gelu_(acc[mi][ni][1] + bs1[c1]);
                g_tdirT[(size_t)c0*Bb + r1] = gelu_(acc[mi][ni][2] + bs1[c0]);
                g_tdirT[(size_t)c1*Bb + r1] = gelu_(acc[mi][ni][3] + bs1[c1]);
            }
        }
        return;
    }

    float dv0[4], dv1[4], dt0[4], dt1[4];
    int   rr0[4], rr1[4];
    #pragma unroll
    for (int mi = 0; mi < 4; mi++){
        rr0[mi] = m0 + wR*64 + mi*16 + gid;  rr1[mi] = rr0[mi] + 8;
        dv0[mi] = (fam == 0) ? days[rr0[mi]] : 0.f;
        dv1[mi] = (fam == 0) ? days[rr1[mi]] : 0.f;
        dt0[mi] = fmaxf(dv0[mi], 0.f);
        dt1[mi] = fmaxf(dv1[mi], 0.f);
    }

    #pragma unroll
    for (int ni = 0; ni < 4; ni++){
        int c0 = n0 + wC*32 + ni*8 + 2*tg, c1 = c0 + 1;
        float v0 = g_v[c0], v1 = g_v[c1];
        float b0 = g_beff[c0], b1 = g_beff[c1];
        int ch = c0 >> 6;                 // c1 shares the channel (c0 even)
        int cc0 = c0 & 63, cc1 = c1 & 63;
        float* Gt = (fam == 0) ? g_gates[ch] : g_gcur[ch];
        #pragma unroll
        for (int mi = 0; mi < 4; mi++){
            float g00 = acc[mi][ni][0] + dv0[mi]*v0 + b0;
            float g01 = acc[mi][ni][1] + dv0[mi]*v1 + b1;
            float g10 = acc[mi][ni][2] + dv1[mi]*v0 + b0;
            float g11 = acc[mi][ni][3] + dv1[mi]*v1 + b1;
            Gt[(size_t)rr0[mi]*Dd + cc0] = act_(g00, ch, dt0[mi]);
            Gt[(size_t)rr0[mi]*Dd + cc1] = act_(g01, ch, dt0[mi]);
            Gt[(size_t)rr1[mi]*Dd + cc0] = act_(g10, ch, dt1[mi]);
            Gt[(size_t)rr1[mi]*Dd + cc1] = act_(g11, ch, dt1[mi]);
        }
    }
}

// ---------------- K2: CT-LSTM scan over L ----------------
__global__ void scan_kernel()
{
    const int b = blockIdx.x;
    const int d = threadIdx.x;            // 64 threads
    const size_t base = (size_t)b * Ll * Dd + d;
    const float* __restrict__ p0 = g_gates[0] + base;
    const float* __restrict__ p1 = g_gates[1] + base;
    const float* __restrict__ p2 = g_gates[2] + base;
    const float* __restrict__ p3 = g_gates[3] + base;
    const float* __restrict__ p4 = g_gates[4] + base;
    const float* __restrict__ p5 = g_gates[5] + base;
    float* __restrict__ ph = g_h + base;
    float c = 0.f;

    for (int l = 0; l < Ll; l += 4){
        size_t o0 = (size_t)l * Dd, o1 = o0 + Dd, o2 = o1 + Dd, o3 = o2 + Dd;
        float i0=p0[o0], f0=p1[o0], z0=p2[o0], oo0=p3[o0], e0=p4[o0], q0=p5[o0];
        float i1=p0[o1], f1=p1[o1], z1=p2[o1], oo1=p3[o1], e1=p4[o1], q1=p5[o1];
        float i2=p0[o2], f2=p1[o2], z2=p2[o2], oo2=p3[o2], e2=p4[o2], q2=p5[o2];
        float i3=p0[o3], f3=p1[o3], z3=p2[o3], oo3=p3[o3], e3=p4[o3], q3=p5[o3];

        c = f0*c + i0*z0; { float cd = q0 + (c - q0)*e0; ph[o0] = oo0 * tanhf(cd); }
        c = f1*c + i1*z1; { float cd = q1 + (c - q1)*e1; ph[o1] = oo1 * tanhf(cd); }
        c = f2*c + i2*z2; { float cd = q2 + (c - q2)*e2; ph[o2] = oo2 * tanhf(cd); }
        c = f3*c + i3*z3; { float cd = q3 + (c - q3)*e3; ph[o3] = oo3 * tanhf(cd); }
    }
    g_clast[b * Dd + d] = c;
}

// ---------------- K3: intensity MLP ----------------
__global__ __launch_bounds__(256) void intensity_kernel(
    int mode,
    const float* __restrict__ Wi1, const float* __restrict__ bi1,
    const float* __restrict__ Wi2, const float* __restrict__ bi2,
    float* __restrict__ out)
{
    __shared__ __align__(16) float Hs[64][68];
    __shared__ __align__(16) float W1c[16][32][4];
    __shared__ float T1s[64][33];

    const float* hin = (mode == 0) ? g_h : g_hcur;
    const int t = threadIdx.x;
    const int r0 = blockIdx.x * 64;

    #pragma unroll
    for (int q = 0; q < 4; q++){
        int f = t + 256*q;
        int row = f >> 4, c4 = (f & 15) * 4;
        *(float4*)&Hs[row][c4] = *(const float4*)(hin + (size_t)(r0 + row) * Dd + c4);
    }
    #pragma unroll
    for (int q = 0; q < 2; q++){
        int f = t + 256*q;
        int k = f >> 3, c4 = (f & 7) * 4;
        float4 w = *(const float4*)(Wi1 + (size_t)k * 32 + c4);
        W1c[k>>2][c4+0][k&3] = w.x;
        W1c[k>>2][c4+1][k&3] = w.y;
        W1c[k>>2][c4+2][k&3] = w.z;
        W1c[k>>2][c4+3][k&3] = w.w;
    }
    __syncthreads();

    const int col = t & 31;
    const int rb  = t >> 5;
    float s[8] = {0,0,0,0,0,0,0,0};
    #pragma unroll
    for (int kc = 0; kc < 16; kc++){
        float4 b = *(const float4*)&W1c[kc][col][0];
        #pragma unroll
        for (int i = 0; i < 8; i++){
            float4 a = *(const float4*)&Hs[rb*8 + i][4*kc];
            s[i] = fmaf(a.x,b.x,fmaf(a.y,b.y,fmaf(a.z,b.z,fmaf(a.w,b.w,s[i]))));
        }
    }
    const float b1 = bi1[col];
    #pragma unroll
    for (int i = 0; i < 8; i++)
        T1s[rb*8 + i][col] = gelu_(s[i] + b1);
    __syncthreads();

    for (int off = t; off < 64 * NS; off += 256){
        int row = off / NS, c = off % NS;
        float ss = bi2[c];
        #pragma unroll 8
        for (int k = 0; k < 32; k++) ss += T1s[row][k] * Wi2[k * NS + c];
        out[(size_t)(r0 + row) * NS + c] = softplus_(ss);
    }
}

// ---------------- K4: current cell update (dt=0 -> c_dec = c) ----------------
__global__ void curcell_kernel()
{
    int i = blockIdx.x * blockDim.x + threadIdx.x;   // Bb*Dd = 16384
    float c = g_gcur[1][i] * g_clast[i] + g_gcur[0][i] * g_gcur[2][i];
    g_hcur[i] = g_gcur[3][i] * tanhf(c);
}

// ---------------- K5: logits + softmax + tte ----------------
__global__ void final_kernel(const float* __restrict__ Ws2, const float* __restrict__ bs2,
                             const float* __restrict__ Wq1, const float* __restrict__ bq1,
                             const float* __restrict__ Wq2, const float* __restrict__ bq2,
                             float* __restrict__ dout)
{
    __shared__ float sW2[G6 * NS];
    __shared__ float sQ1[Dd * 32];
    int b = threadIdx.x;

    for (int i = b; i < G6 * NS; i += 256) sW2[i] = Ws2[i];
    for (int i = b; i < Dd * 32; i += 256) sQ1[i] = Wq1[i];
    __syncthreads();

    float lg[NS];
    #pragma unroll
    for (int c = 0; c < NS; c++) lg[c] = bs2[c];
    #pragma unroll 4
    for (int k = 0; k < G6; k++){
        float tv = g_tdirT[(size_t)k * Bb + b];
        #pragma unroll
        for (int c = 0; c < NS; c++) lg[c] += tv * sW2[k * NS + c];
    }

    const float* ci = dout + OFF_CI + (size_t)b * NS;
    float li[NS], mx = -1e30f;
    #pragma unroll
    for (int c = 0; c < NS; c++){ li[c] = lg[c] + logf(ci[c]); mx = fmaxf(mx, li[c]); }
    float den = 0.f, ex[NS];
    #pragma unroll
    for (int c = 0; c < NS; c++){ ex[c] = expf(li[c] - mx); den += ex[c]; }
    float inv = 1.f / den;
    #pragma unroll
    for (int c = 0; c < NS; c++) dout[OFF_PROBS + (size_t)b * NS + c] = ex[c] * inv;

    float t2[32];
    #pragma unroll
    for (int c = 0; c < 32; c++) t2[c] = bq1[c];
    const float* hr = g_hcur + (size_t)b * Dd;
    #pragma unroll 4
    for (int k = 0; k < Dd; k++){
        float hv = hr[k];
        #pragma unroll
        for (int c = 0; c < 32; c++) t2[c] += hv * sQ1[k * 32 + c];
    }
    float q = bq2[0];
    #pragma unroll
    for (int c = 0; c < 32; c++) q += gelu_(t2[c]) * Wq2[c];
    dout[OFF_TTE + b] = softplus_(q);
}

// ---------------- launch ----------------
extern "C" void kernel_launch(void* const* d_in, const int* in_sizes, int n_in,
                              void* d_out, int out_size)
{
    const float* cls   = (const float*)d_in[0];
    const float* ev    = (const float*)d_in[1];
    const float* days  = (const float*)d_in[2];
    const float* We    = (const float*)d_in[3];
    const float* be    = (const float*)d_in[4];
    const float* Wtime = (const float*)d_in[5];
    const float* btime = (const float*)d_in[6];
    const float* Wg    = (const float*)d_in[7];
    const float* bg    = (const float*)d_in[8];
    const float* Wi1   = (const float*)d_in[9];
    const float* bi1   = (const float*)d_in[10];
    const float* Wi2   = (const float*)d_in[11];
    const float* bi2   = (const float*)d_in[12];
    const float* Ws1   = (const float*)d_in[13];
    const float* bs1   = (const float*)d_in[14];
    const float* Ws2   = (const float*)d_in[15];
    const float* bs2   = (const float*)d_in[16];
    const float* Wq1   = (const float*)d_in[17];
    const float* bq1   = (const float*)d_in[18];
    const float* Wq2   = (const float*)d_in[19];
    const float* bq2   = (const float*)d_in[20];
    float* dout = (float*)d_out;

    prep_kernel<<<1, G6>>>(Wtime, btime, Wg, bg, be);
    wc_kernel<<<Hh, G6>>>(We, Wg);

    // 1200 gate blocks + 6 direct-logit blocks + 4 current-gate blocks
    mma3_kernel<<<1210, 256>>>(ev, cls, days, Ws1, bs1);

    scan_kernel<<<Bb, Dd>>>();

    intensity_kernel<<<Mm/64, 256>>>(0, Wi1, bi1, Wi2, bi2, dout + OFF_HIST);

    curcell_kernel<<<32, 512>>>();

    intensity_kernel<<<Bb/64, 256>>>(1, Wi1, bi1, Wi2, bi2, dout + OFF_CI);

    final_kernel<<<1, Bb>>>(Ws2, bs2, Wq1, bq1, Wq2, bq2, dout);
}

// round 7
// speedup vs baseline: 1.6778x; 1.6778x over previous
#include <cuda_runtime.h>
#include <math.h>

#define Bb 256
#define Ll 200
#define Hh 768
#define Dd 64
#define Mm (Bb*Ll)          // 51200
#define G6 384
#define NS 6

#define OFF_PROBS 0
#define OFF_TTE   1536
#define OFF_CI    1792
#define OFF_HIST  3328

// ---------------- scratch (device globals; no allocation) ----------------
__device__ __align__(16) float g_gi[(size_t)Mm*G6];      // interleaved gates [row][ch*64+d]
__device__ __align__(16) float g_h[(size_t)Mm*Dd];
__device__ __align__(16) float g_clast[Bb*Dd];
__device__ __align__(16) float g_gcur[4][Bb*Dd];
__device__ __align__(16) float g_hcur[Bb*Dd];
__device__ __align__(16) float g_ecur[Bb*Dd];
__device__ __align__(16) float g_tdirT[(size_t)G6*Bb];   // [col][b]
__device__ __align__(16) float g_v[G6];
__device__ __align__(16) float g_beff[G6];
__device__ __align__(16) float g_W1c[2048];              // packed Wi1 [16][32][4]

// ---------------- math helpers ----------------
__device__ __forceinline__ float sigm_(float x){ return 1.f/(1.f+expf(-x)); }
__device__ __forceinline__ float softplus_(float x){
    return (x > 0.f) ? (x + log1pf(expf(-x))) : log1pf(expf(x));
}
__device__ __forceinline__ float gelu_(float x){
    return 0.5f * x * (1.f + erff(x * 0.70710678118654752440f));
}

// ---------------- K0 (idx 0): rank-1 time-feature folding ----------------
__global__ void prep_kernel(const float* __restrict__ Wtime, const float* __restrict__ btime,
                            const float* __restrict__ Wg, const float* __restrict__ bg)
{
    int j = threadIdx.x;
    if (j >= G6) return;
    float v = 0.f, bf = bg[j];
    #pragma unroll 8
    for (int d = 0; d < Dd; d++){
        float w = Wg[(size_t)(Dd + d) * G6 + j];
        v  += Wtime[d] * w;
        bf += btime[d] * w;
    }
    g_v[j] = v;
    g_beff[j] = bf;
}

// ---------------- K0b (idx 1): pack Wi1 -> [16][32][4] ----------------
__global__ void pack_w1_kernel(const float* __restrict__ Wi1)
{
    int f = threadIdx.x;           // 512 threads
    int k = f >> 3, c4 = (f & 7) * 4;
    float4 w = *(const float4*)(Wi1 + (size_t)k * 32 + c4);
    int kc = k >> 2, kk = k & 3;
    g_W1c[kc*128 + (c4+0)*4 + kk] = w.x;
    g_W1c[kc*128 + (c4+1)*4 + kk] = w.y;
    g_W1c[kc*128 + (c4+2)*4 + kk] = w.z;
    g_W1c[kc*128 + (c4+3)*4 + kk] = w.w;
}

// ---------------- K0c (idx 2): E_cur = cls@We + be ----------------
__global__ void ecur_kernel(const float* __restrict__ cls,
                            const float* __restrict__ We, const float* __restrict__ be)
{
    int b = blockIdx.x * 4 + (threadIdx.x >> 6);
    int d = threadIdx.x & 63;
    float s = be[d];
    const float* xr = cls + (size_t)b * Hh;
    #pragma unroll 4
    for (int k = 0; k < Hh; k += 4){
        float4 x = *(const float4*)(xr + k);
        s = fmaf(x.x, We[(size_t)(k+0)*Dd + d], s);
        s = fmaf(x.y, We[(size_t)(k+1)*Dd + d], s);
        s = fmaf(x.z, We[(size_t)(k+2)*Dd + d], s);
        s = fmaf(x.w, We[(size_t)(k+3)*Dd + d], s);
    }
    g_ecur[b * Dd + d] = s;
}

// ---------------- K1 (idx 3): fused  E = X@We ; g = E@WgE + days*v + beff ----
// grid 412: blocks [0,400): event rows, tile 128x64 -> g_gi (interleaved).
//           blocks [400,412): gelu(cls@Ws1+bs1) 128x64 tiles -> g_tdirT.
#define FMA4(acc0,acc1,acc2,acc3) \
    acc0 = fmaf(a.x,b0.x,fmaf(a.y,b1.x,fmaf(a.z,b2.x,fmaf(a.w,b3.x,acc0)))); \
    acc1 = fmaf(a.x,b0.y,fmaf(a.y,b1.y,fmaf(a.z,b2.y,fmaf(a.w,b3.y,acc1)))); \
    acc2 = fmaf(a.x,b0.z,fmaf(a.y,b1.z,fmaf(a.z,b2.z,fmaf(a.w,b3.z,acc2)))); \
    acc3 = fmaf(a.x,b0.w,fmaf(a.y,b1.w,fmaf(a.z,b2.w,fmaf(a.w,b3.w,acc3))));

__global__ void __launch_bounds__(256, 3) fused_main_kernel(
    const float* __restrict__ Xev, const float* __restrict__ days,
    const float* __restrict__ cls,
    const float* __restrict__ We,  const float* __restrict__ be,
    const float* __restrict__ Wg,
    const float* __restrict__ Ws1, const float* __restrict__ bs1)
{
    extern __shared__ float sm[];
    float* Xs  = sm;          // [2][128][8]   2048 floats
    float* Wts = sm + 2048;   // [2][8][64]    1024 floats
    float* CW  = sm;          // alias: [64][64] 4096 floats
    float* Es  = sm + 4096;   // [128][64]     8192 floats

    const int t  = threadIdx.x;
    const int tx = t & 15;
    const int ty = t >> 4;
    const int bx = blockIdx.x;
    const bool gp = (bx >= 400);

    const float* X; const float* W; int m0, c0, ldw;
    if (gp){ int idx = bx - 400; m0 = (idx & 1) * 128; c0 = (idx >> 1) * 64; X = cls; W = Ws1; ldw = G6; }
    else   { m0 = bx * 128; c0 = 0; X = Xev; W = We; ldw = Dd; }

    float acc[8][4];
    #pragma unroll
    for (int i=0;i<8;i++){ acc[i][0]=0.f; acc[i][1]=0.f; acc[i][2]=0.f; acc[i][3]=0.f; }

    const int arow = t >> 1,  ac4 = (t & 1) * 4;
    const int brow = t >> 4,  bc4 = (t & 15) * 4;   // brow valid when t < 128

    const float* Xr = X + (size_t)(m0 + arow) * Hh + ac4;
    const float* Wr = W + (size_t)brow * ldw + c0 + bc4;

    float4 xa = *(const float4*)(Xr);
    float4 wb;
    if (t < 128) wb = *(const float4*)(Wr);
    *(float4*)&Xs[arow*8 + ac4] = xa;
    if (t < 128) *(float4*)&Wts[brow*64 + bc4] = wb;
    __syncthreads();

    const int NT = Hh / 8;   // 96 k-tiles
    for (int kt = 0; kt < NT; kt++){
        const int cur = kt & 1, nxt = cur ^ 1;
        if (kt < NT - 1){
            int k0 = 8*(kt+1);
            xa = *(const float4*)(Xr + k0);
            if (t < 128) wb = *(const float4*)(Wr + (size_t)k0 * ldw);
        }
        const float* Xc = Xs + cur*1024;
        const float* Wc = Wts + cur*512;
        #pragma unroll
        for (int kc = 0; kc < 2; kc++){
            float4 b0 = *(const float4*)&Wc[(4*kc+0)*64 + 4*tx];
            float4 b1 = *(const float4*)&Wc[(4*kc+1)*64 + 4*tx];
            float4 b2 = *(const float4*)&Wc[(4*kc+2)*64 + 4*tx];
            float4 b3 = *(const float4*)&Wc[(4*kc+3)*64 + 4*tx];
            #pragma unroll
            for (int i = 0; i < 8; i++){
                float4 a = *(const float4*)&Xc[(ty+16*i)*8 + 4*kc];
                FMA4(acc[i][0], acc[i][1], acc[i][2], acc[i][3])
            }
        }
        if (kt < NT - 1){
            float* Xn = Xs + nxt*1024;
            float* Wn = Wts + nxt*512;
            *(float4*)&Xn[arow*8 + ac4] = xa;
            if (t < 128) *(float4*)&Wn[brow*64 + bc4] = wb;
        }
        __syncthreads();
    }

    if (gp){
        #pragma unroll
        for (int i = 0; i < 8; i++){
            int row = m0 + ty + 16*i;
            #pragma unroll
            for (int j = 0; j < 4; j++){
                int col = c0 + 4*tx + j;
                g_tdirT[(size_t)col * Bb + row] = gelu_(acc[i][j] + bs1[col]);
            }
        }
        return;
    }

    // stage E (+be) into smem; capture days
    float4 be4 = *(const float4*)(be + 4*tx);
    float dval[8], dtv[8];
    #pragma unroll
    for (int i = 0; i < 8; i++){
        float4 v = make_float4(acc[i][0]+be4.x, acc[i][1]+be4.y, acc[i][2]+be4.z, acc[i][3]+be4.w);
        *(float4*)&Es[(ty+16*i)*64 + 4*tx] = v;
        dval[i] = days[m0 + ty + 16*i];
        dtv[i]  = fmaxf(dval[i], 0.f);
    }
    __syncthreads();

    for (int gc = 0; gc < 6; gc++){
        #pragma unroll
        for (int q = 0; q < 4; q++){
            int f = t + 256*q;
            int r = f >> 4, c4 = (f & 15) * 4;
            *(float4*)&CW[r*64 + c4] = *(const float4*)(Wg + (size_t)r * G6 + gc*64 + c4);
        }
        __syncthreads();

        float vv[4], bf[4];
        #pragma unroll
        for (int j = 0; j < 4; j++){
            vv[j] = g_v[gc*64 + 4*tx + j];
            bf[j] = g_beff[gc*64 + 4*tx + j];
        }

        float r8[8][4];
        #pragma unroll
        for (int i=0;i<8;i++){ r8[i][0]=0.f; r8[i][1]=0.f; r8[i][2]=0.f; r8[i][3]=0.f; }

        #pragma unroll 4
        for (int kc = 0; kc < 16; kc++){
            float4 b0 = *(const float4*)&CW[(4*kc+0)*64 + 4*tx];
            float4 b1 = *(const float4*)&CW[(4*kc+1)*64 + 4*tx];
            float4 b2 = *(const float4*)&CW[(4*kc+2)*64 + 4*tx];
            float4 b3 = *(const float4*)&CW[(4*kc+3)*64 + 4*tx];
            #pragma unroll
            for (int i = 0; i < 8; i++){
                float4 a = *(const float4*)&Es[(ty+16*i)*64 + 4*kc];
                FMA4(r8[i][0], r8[i][1], r8[i][2], r8[i][3])
            }
        }

        #pragma unroll
        for (int i = 0; i < 8; i++){
            float gv[4], ov[4];
            #pragma unroll
            for (int j = 0; j < 4; j++)
                gv[j] = r8[i][j] + dval[i]*vv[j] + bf[j];
            if (gc == 2){
                #pragma unroll
                for (int j = 0; j < 4; j++) ov[j] = tanhf(gv[j]);
            } else if (gc == 4){
                #pragma unroll
                for (int j = 0; j < 4; j++) ov[j] = expf(-softplus_(gv[j]) * dtv[i]);
            } else if (gc == 5){
                #pragma unroll
                for (int j = 0; j < 4; j++) ov[j] = gv[j];
            } else {
                #pragma unroll
                for (int j = 0; j < 4; j++) ov[j] = sigm_(gv[j]);
            }
            float4 o4 = make_float4(ov[0], ov[1], ov[2], ov[3]);
            *(float4*)(g_gi + (size_t)(m0 + ty + 16*i) * G6 + gc*64 + 4*tx) = o4;
        }
        __syncthreads();
    }
}

// ---------------- K2 (idx 4): CT-LSTM scan, 8-step unroll, interleaved reads ----
__global__ void __launch_bounds__(64) scan_kernel()
{
    const int b = blockIdx.x;
    const int d = threadIdx.x;            // 64 threads
    const float* __restrict__ gp = g_gi + (size_t)b * Ll * G6 + d;
    float* __restrict__ ph = g_h + (size_t)b * Ll * Dd + d;
    float c = 0.f;

    for (int l0 = 0; l0 < Ll; l0 += 8){
        float gv[8][6];
        #pragma unroll
        for (int s = 0; s < 8; s++){
            const float* p = gp + (size_t)(l0 + s) * G6;
            #pragma unroll
            for (int ch = 0; ch < 6; ch++) gv[s][ch] = p[ch * 64];
        }
        #pragma unroll
        for (int s = 0; s < 8; s++){
            c = gv[s][1]*c + gv[s][0]*gv[s][2];
            float cd = gv[s][5] + (c - gv[s][5]) * gv[s][4];
            ph[(size_t)(l0 + s) * Dd] = gv[s][3] * tanhf(cd);
        }
    }
    g_clast[b * Dd + d] = c;
}

// ---------------- K3 (idx 5): intensity MLP ----------------
__global__ __launch_bounds__(256) void intensity_kernel(
    int mode,
    const float* __restrict__ bi1,
    const float* __restrict__ Wi2, const float* __restrict__ bi2,
    float* __restrict__ out)
{
    __shared__ __align__(16) float Hs[64][68];
    __shared__ __align__(16) float W1s[2048];   // packed [16][32][4]
    __shared__ float T1s[64][33];

    const float* hin = (mode == 0) ? g_h : g_hcur;
    const int t = threadIdx.x;
    const int r0 = blockIdx.x * 64;

    #pragma unroll
    for (int q = 0; q < 4; q++){
        int f = t + 256*q;
        int row = f >> 4, c4 = (f & 15) * 4;
        *(float4*)&Hs[row][c4] = *(const float4*)(hin + (size_t)(r0 + row) * Dd + c4);
    }
    #pragma unroll
    for (int q = 0; q < 2; q++){
        int f = t + 256*q;
        ((float4*)W1s)[f] = ((const float4*)g_W1c)[f];
    }
    __syncthreads();

    const int col = t & 31;
    const int rb  = t >> 5;
    float s[8] = {0,0,0,0,0,0,0,0};
    #pragma unroll
    for (int kc = 0; kc < 16; kc++){
        float4 b = *(const float4*)&W1s[kc*128 + col*4];
        #pragma unroll
        for (int i = 0; i < 8; i++){
            float4 a = *(const float4*)&Hs[rb*8 + i][4*kc];
            s[i] = fmaf(a.x,b.x,fmaf(a.y,b.y,fmaf(a.z,b.z,fmaf(a.w,b.w,s[i]))));
        }
    }
    const float b1 = bi1[col];
    #pragma unroll
    for (int i = 0; i < 8; i++)
        T1s[rb*8 + i][col] = gelu_(s[i] + b1);
    __syncthreads();

    for (int off = t; off < 64 * NS; off += 256){
        int row = off / NS, c = off % NS;
        float ss = bi2[c];
        #pragma unroll 8
        for (int k = 0; k < 32; k++) ss += T1s[row][k] * Wi2[k * NS + c];
        out[(size_t)(r0 + row) * NS + c] = softplus_(ss);
    }
}

// ---------------- K4b: current-step gates (dt=0, channels i,f,z,o) ----------------
__global__ void gcur_kernel(const float* __restrict__ Wg)
{
    __shared__ float Er[64];
    int b = blockIdx.x, col = threadIdx.x;   // 256 threads -> channels 0..3
    if (col < 64) Er[col] = g_ecur[b * Dd + col];
    __syncthreads();
    float s = g_beff[col];
    #pragma unroll 8
    for (int k = 0; k < 64; k++) s = fmaf(Er[k], Wg[(size_t)k * G6 + col], s);
    int ch = col >> 6, cc = col & 63;
    float o = (ch == 2) ? tanhf(s) : sigm_(s);
    g_gcur[ch][b * Dd + cc] = o;
}

// ---------------- K4c: current cell update (dt=0 -> c_dec = c) ----------------
__global__ void curcell_kernel()
{
    int i = blockIdx.x * blockDim.x + threadIdx.x;   // Bb*Dd = 16384
    float c = g_gcur[1][i] * g_clast[i] + g_gcur[0][i] * g_gcur[2][i];
    g_hcur[i] = g_gcur[3][i] * tanhf(c);
}

// ---------------- K5: logits + softmax + tte ----------------
__global__ void final_kernel(const float* __restrict__ Ws2, const float* __restrict__ bs2,
                             const float* __restrict__ Wq1, const float* __restrict__ bq1,
                             const float* __restrict__ Wq2, const float* __restrict__ bq2,
                             float* __restrict__ dout)
{
    __shared__ float sW2[G6 * NS];
    __shared__ float sQ1[Dd * 32];
    int b = threadIdx.x;

    for (int i = b; i < G6 * NS; i += 256) sW2[i] = Ws2[i];
    for (int i = b; i < Dd * 32; i += 256) sQ1[i] = Wq1[i];
    __syncthreads();

    float lg[NS];
    #pragma unroll
    for (int c = 0; c < NS; c++) lg[c] = bs2[c];
    #pragma unroll 4
    for (int k = 0; k < G6; k++){
        float tv = g_tdirT[(size_t)k * Bb + b];
        #pragma unroll
        for (int c = 0; c < NS; c++) lg[c] += tv * sW2[k * NS + c];
    }

    const float* ci = dout + OFF_CI + (size_t)b * NS;
    float li[NS], mx = -1e30f;
    #pragma unroll
    for (int c = 0; c < NS; c++){ li[c] = lg[c] + logf(ci[c]); mx = fmaxf(mx, li[c]); }
    float den = 0.f, ex[NS];
    #pragma unroll
    for (int c = 0; c < NS; c++){ ex[c] = expf(li[c] - mx); den += ex[c]; }
    float inv = 1.f / den;
    #pragma unroll
    for (int c = 0; c < NS; c++) dout[OFF_PROBS + (size_t)b * NS + c] = ex[c] * inv;

    float t2[32];
    #pragma unroll
    for (int c = 0; c < 32; c++) t2[c] = bq1[c];
    const float* hr = g_hcur + (size_t)b * Dd;
    #pragma unroll 4
    for (int k = 0; k < Dd; k++){
        float hv = hr[k];
        #pragma unroll
        for (int c = 0; c < 32; c++) t2[c] += hv * sQ1[k * 32 + c];
    }
    float q = bq2[0];
    #pragma unroll
    for (int c = 0; c < 32; c++) q += gelu_(t2[c]) * Wq2[c];
    dout[OFF_TTE + b] = softplus_(q);
}

// ---------------- launch ----------------
extern "C" void kernel_launch(void* const* d_in, const int* in_sizes, int n_in,
                              void* d_out, int out_size)
{
    const float* cls   = (const float*)d_in[0];
    const float* ev    = (const float*)d_in[1];
    const float* days  = (const float*)d_in[2];
    const float* We    = (const float*)d_in[3];
    const float* be    = (const float*)d_in[4];
    const float* Wtime = (const float*)d_in[5];
    const float* btime = (const float*)d_in[6];
    const float* Wg    = (const float*)d_in[7];
    const float* bg    = (const float*)d_in[8];
    const float* Wi1   = (const float*)d_in[9];
    const float* bi1   = (const float*)d_in[10];
    const float* Wi2   = (const float*)d_in[11];
    const float* bi2   = (const float*)d_in[12];
    const float* Ws1   = (const float*)d_in[13];
    const float* bs1   = (const float*)d_in[14];
    const float* Ws2   = (const float*)d_in[15];
    const float* bs2   = (const float*)d_in[16];
    const float* Wq1   = (const float*)d_in[17];
    const float* bq1   = (const float*)d_in[18];
    const float* Wq2   = (const float*)d_in[19];
    const float* bq2   = (const float*)d_in[20];
    float* dout = (float*)d_out;

    const int SMEM = 12288 * 4;   // 49152 B dynamic smem (default limit)

    prep_kernel<<<1, G6>>>(Wtime, btime, Wg, bg);          // idx 0
    pack_w1_kernel<<<1, 512>>>(Wi1);                       // idx 1
    ecur_kernel<<<Bb/4, 256>>>(cls, We, be);               // idx 2

    fused_main_kernel<<<412, 256, SMEM>>>(ev, days, cls, We, be, Wg, Ws1, bs1);  // idx 3 (profiled)

    scan_kernel<<<Bb, Dd>>>();                             // idx 4

    intensity_kernel<<<Mm/64, 256>>>(0, bi1, Wi2, bi2, dout + OFF_HIST);

    gcur_kernel<<<Bb, 256>>>(Wg);
    curcell_kernel<<<32, 512>>>();

    intensity_kernel<<<Bb/64, 256>>>(1, bi1, Wi2, bi2, dout + OFF_CI);

    final_kernel<<<1, Bb>>>(Ws2, bs2, Wq1, bq1, Wq2, bq2, dout);
}

// round 8
// speedup vs baseline: 1.7835x; 1.0630x over previous
#include <cuda_runtime.h>
#include <math.h>

#define Bb 256
#define Ll 200
#define Hh 768
#define Dd 64
#define Mm (Bb*Ll)          // 51200
#define G6 384
#define NS 6

#define OFF_PROBS 0
#define OFF_TTE   1536
#define OFF_CI    1792
#define OFF_HIST  3328

// ---------------- scratch (device globals; no allocation) ----------------
__device__ __align__(16) float g_gi[(size_t)Mm*G6];      // interleaved gates [row][ch*64+d]
__device__ __align__(16) float g_clast[Bb*Dd];
__device__ __align__(16) float g_hcur[Bb*Dd];
__device__ __align__(16) float g_ecur[Bb*Dd];
__device__ __align__(16) float g_tdirT[(size_t)G6*Bb];   // [col][b]
__device__ __align__(16) float g_v[G6];
__device__ __align__(16) float g_beff[G6];
__device__ __align__(16) float g_W1c[2048];              // packed Wi1 [16][32][4]

// ---------------- math helpers ----------------
__device__ __forceinline__ float sigm_(float x){ return 1.f/(1.f+expf(-x)); }
__device__ __forceinline__ float softplus_(float x){
    return (x > 0.f) ? (x + log1pf(expf(-x))) : log1pf(expf(x));
}
__device__ __forceinline__ float gelu_(float x){
    return 0.5f * x * (1.f + erff(x * 0.70710678118654752440f));
}

// ---------------- K0 (idx 0): rank-1 folds + Wi1 pack ----------------
__global__ void prep_pack_kernel(const float* __restrict__ Wtime, const float* __restrict__ btime,
                                 const float* __restrict__ Wg, const float* __restrict__ bg,
                                 const float* __restrict__ Wi1)
{
    int t = threadIdx.x;   // 512
    if (t < G6){
        float v = 0.f, bf = bg[t];
        #pragma unroll 8
        for (int d = 0; d < Dd; d++){
            float w = Wg[(size_t)(Dd + d) * G6 + t];
            v  += Wtime[d] * w;
            bf += btime[d] * w;
        }
        g_v[t] = v;
        g_beff[t] = bf;
    }
    {
        int k = t >> 3, c4 = (t & 7) * 4;
        float4 w = *(const float4*)(Wi1 + (size_t)k * 32 + c4);
        int kc = k >> 2, kk = k & 3;
        g_W1c[kc*128 + (c4+0)*4 + kk] = w.x;
        g_W1c[kc*128 + (c4+1)*4 + kk] = w.y;
        g_W1c[kc*128 + (c4+2)*4 + kk] = w.z;
        g_W1c[kc*128 + (c4+3)*4 + kk] = w.w;
    }
}

// ---------------- K1 (idx 1): E_cur = cls@We + be ----------------
__global__ void ecur_kernel(const float* __restrict__ cls,
                            const float* __restrict__ We, const float* __restrict__ be)
{
    int b = blockIdx.x * 4 + (threadIdx.x >> 6);
    int d = threadIdx.x & 63;
    float s = be[d];
    const float* xr = cls + (size_t)b * Hh;
    #pragma unroll 4
    for (int k = 0; k < Hh; k += 4){
        float4 x = *(const float4*)(xr + k);
        s = fmaf(x.x, We[(size_t)(k+0)*Dd + d], s);
        s = fmaf(x.y, We[(size_t)(k+1)*Dd + d], s);
        s = fmaf(x.z, We[(size_t)(k+2)*Dd + d], s);
        s = fmaf(x.w, We[(size_t)(k+3)*Dd + d], s);
    }
    g_ecur[b * Dd + d] = s;
}

// ---------------- K2 (idx 2): fused  E = X@We ; g = E@WgE + days*v + beff ----
// grid 412: blocks [0,400): event rows, tile 128x64 -> g_gi (interleaved).
//           blocks [400,412): gelu(cls@Ws1+bs1) 128x64 tiles -> g_tdirT.
// smem: buffers [0,6144) (Xs [2][128][16], Wts [2][16][64]); CW aliases [0,4096);
//       Es [128][64] at [6144,14336). 57344 B total (needs opt-in).
#define FMA4(acc0,acc1,acc2,acc3) \
    acc0 = fmaf(a.x,b0.x,fmaf(a.y,b1.x,fmaf(a.z,b2.x,fmaf(a.w,b3.x,acc0)))); \
    acc1 = fmaf(a.x,b0.y,fmaf(a.y,b1.y,fmaf(a.z,b2.y,fmaf(a.w,b3.y,acc1)))); \
    acc2 = fmaf(a.x,b0.z,fmaf(a.y,b1.z,fmaf(a.z,b2.z,fmaf(a.w,b3.z,acc2)))); \
    acc3 = fmaf(a.x,b0.w,fmaf(a.y,b1.w,fmaf(a.z,b2.w,fmaf(a.w,b3.w,acc3))));

__global__ void __launch_bounds__(256, 3) fused_main_kernel(
    const float* __restrict__ Xev, const float* __restrict__ days,
    const float* __restrict__ cls,
    const float* __restrict__ We,  const float* __restrict__ be,
    const float* __restrict__ Wg,
    const float* __restrict__ Ws1, const float* __restrict__ bs1)
{
    extern __shared__ float sm[];
    float* Xs  = sm;          // [2][128][16]  4096 floats
    float* Wts = sm + 4096;   // [2][16][64]   2048 floats
    float* CW  = sm;          // alias: [64][64] 4096 floats
    float* Es  = sm + 6144;   // [128][64]     8192 floats

    const int t  = threadIdx.x;
    const int tx = t & 15;
    const int ty = t >> 4;
    const int bx = blockIdx.x;
    const bool gp = (bx >= 400);

    const float* X; const float* W; int m0, c0, ldw;
    if (gp){ int idx = bx - 400; m0 = (idx & 1) * 128; c0 = (idx >> 1) * 64; X = cls; W = Ws1; ldw = G6; }
    else   { m0 = bx * 128; c0 = 0; X = Xev; W = We; ldw = Dd; }

    float acc[8][4];
    #pragma unroll
    for (int i=0;i<8;i++){ acc[i][0]=0.f; acc[i][1]=0.f; acc[i][2]=0.f; acc[i][3]=0.f; }

    // loaders: Xs tile 128x16 -> 512 float4 (2/thread); Wts 16x64 -> 256 float4 (1/thread)
    const int arow = t >> 2,  akq = (t & 3) * 4;
    const int brow = t >> 4,  bc4 = (t & 15) * 4;

    const float* Xr0 = X + (size_t)(m0 + arow) * Hh + akq;
    const float* Xr1 = Xr0 + (size_t)64 * Hh;
    const float* Wr  = W + (size_t)brow * ldw + c0 + bc4;

    // tile 0
    {
        float4 a0 = *(const float4*)(Xr0);
        float4 a1 = *(const float4*)(Xr1);
        float4 b  = *(const float4*)(Wr);
        *(float4*)&Xs[arow*16 + akq]      = a0;
        *(float4*)&Xs[(arow+64)*16 + akq] = a1;
        *(float4*)&Wts[brow*64 + bc4]     = b;
    }
    __syncthreads();

    const int NT = Hh / 16;   // 48 k-tiles
    for (int kt = 0; kt < NT; kt++){
        const int cur = kt & 1;
        if (kt < NT - 1){
            int k0 = 16*(kt+1);
            float4 a0 = *(const float4*)(Xr0 + k0);
            float4 a1 = *(const float4*)(Xr1 + k0);
            float4 b  = *(const float4*)(Wr + (size_t)k0 * ldw);
            float* Xn = Xs + (cur^1)*2048;
            float* Wn = Wts + (cur^1)*1024;
            *(float4*)&Xn[arow*16 + akq]      = a0;
            *(float4*)&Xn[(arow+64)*16 + akq] = a1;
            *(float4*)&Wn[brow*64 + bc4]      = b;
        }
        const float* Xc = Xs + cur*2048;
        const float* Wc = Wts + cur*1024;
        #pragma unroll
        for (int kc = 0; kc < 4; kc++){
            float4 b0 = *(const float4*)&Wc[(4*kc+0)*64 + 4*tx];
            float4 b1 = *(const float4*)&Wc[(4*kc+1)*64 + 4*tx];
            float4 b2 = *(const float4*)&Wc[(4*kc+2)*64 + 4*tx];
            float4 b3 = *(const float4*)&Wc[(4*kc+3)*64 + 4*tx];
            #pragma unroll
            for (int i = 0; i < 8; i++){
                float4 a = *(const float4*)&Xc[(ty+16*i)*16 + 4*kc];
                FMA4(acc[i][0], acc[i][1], acc[i][2], acc[i][3])
            }
        }
        __syncthreads();
    }

    if (gp){
        #pragma unroll
        for (int i = 0; i < 8; i++){
            int row = m0 + ty + 16*i;
            #pragma unroll
            for (int j = 0; j < 4; j++){
                int col = c0 + 4*tx + j;
                g_tdirT[(size_t)col * Bb + row] = gelu_(acc[i][j] + bs1[col]);
            }
        }
        return;
    }

    // stage E (+be) into smem; capture days
    float4 be4 = *(const float4*)(be + 4*tx);
    float dval[8], dtv[8];
    #pragma unroll
    for (int i = 0; i < 8; i++){
        float4 v = make_float4(acc[i][0]+be4.x, acc[i][1]+be4.y, acc[i][2]+be4.z, acc[i][3]+be4.w);
        *(float4*)&Es[(ty+16*i)*64 + 4*tx] = v;
        dval[i] = days[m0 + ty + 16*i];
        dtv[i]  = fmaxf(dval[i], 0.f);
    }
    __syncthreads();

    for (int gc = 0; gc < 6; gc++){
        #pragma unroll
        for (int q = 0; q < 4; q++){
            int f = t + 256*q;
            int r = f >> 4, c4 = (f & 15) * 4;
            *(float4*)&CW[r*64 + c4] = *(const float4*)(Wg + (size_t)r * G6 + gc*64 + c4);
        }
        __syncthreads();

        float vv[4], bf[4];
        #pragma unroll
        for (int j = 0; j < 4; j++){
            vv[j] = g_v[gc*64 + 4*tx + j];
            bf[j] = g_beff[gc*64 + 4*tx + j];
        }

        float r8[8][4];
        #pragma unroll
        for (int i=0;i<8;i++){ r8[i][0]=0.f; r8[i][1]=0.f; r8[i][2]=0.f; r8[i][3]=0.f; }

        #pragma unroll 4
        for (int kc = 0; kc < 16; kc++){
            float4 b0 = *(const float4*)&CW[(4*kc+0)*64 + 4*tx];
            float4 b1 = *(const float4*)&CW[(4*kc+1)*64 + 4*tx];
            float4 b2 = *(const float4*)&CW[(4*kc+2)*64 + 4*tx];
            float4 b3 = *(const float4*)&CW[(4*kc+3)*64 + 4*tx];
            #pragma unroll
            for (int i = 0; i < 8; i++){
                float4 a = *(const float4*)&Es[(ty+16*i)*64 + 4*kc];
                FMA4(r8[i][0], r8[i][1], r8[i][2], r8[i][3])
            }
        }

        #pragma unroll
        for (int i = 0; i < 8; i++){
            float gvv[4], ov[4];
            #pragma unroll
            for (int j = 0; j < 4; j++)
                gvv[j] = r8[i][j] + dval[i]*vv[j] + bf[j];
            if (gc == 2){
                #pragma unroll
                for (int j = 0; j < 4; j++) ov[j] = tanhf(gvv[j]);
            } else if (gc == 4){
                #pragma unroll
                for (int j = 0; j < 4; j++) ov[j] = expf(-softplus_(gvv[j]) * dtv[i]);
            } else if (gc == 5){
                #pragma unroll
                for (int j = 0; j < 4; j++) ov[j] = gvv[j];
            } else {
                #pragma unroll
                for (int j = 0; j < 4; j++) ov[j] = sigm_(gvv[j]);
            }
            float4 o4 = make_float4(ov[0], ov[1], ov[2], ov[3]);
            *(float4*)(g_gi + (size_t)(m0 + ty + 16*i) * G6 + gc*64 + 4*tx) = o4;
        }
        __syncthreads();
    }
}

// ---------------- K3 (idx 3): CT-LSTM scan + fused intensity MLP ----------------
// 64 threads = lanes d. Per 8-step chunk: recurrence -> h_s smem -> layer1
// (thread t: step t>>3, cols (t&7)+8m) -> tt smem -> layer2 (threads 16..63:
// (s,c) = ((t-16)/6,(t-16)%6)) -> history intensity directly to dout.
__global__ void __launch_bounds__(64) scan_int_kernel(
    const float* __restrict__ Wi1, const float* __restrict__ bi1,
    const float* __restrict__ Wi2, const float* __restrict__ bi2,
    float* __restrict__ outHist)
{
    __shared__ __align__(16) float sW1[32*68];   // [col][k], stride 68
    __shared__ float sW2[32*NS];
    __shared__ __align__(16) float h_s[8*68];    // [step][d], stride 68
    __shared__ float tt[8*32];                   // [step][col]

    const int b = blockIdx.x;
    const int t = threadIdx.x;   // 0..63

    for (int u = t; u < 2048; u += 64){ int k = u >> 5, j = u & 31; sW1[j*68 + k] = Wi1[u]; }
    for (int u = t; u < 32*NS; u += 64) sW2[u] = Wi2[u];

    const int s_my = t >> 3, j4 = t & 7;
    float b1v[4];
    #pragma unroll
    for (int m = 0; m < 4; m++) b1v[m] = bi1[j4 + 8*m];
    const bool do2 = (t >= 16);
    const int s2 = (t - 16) / NS, c2 = (t - 16) % NS;
    const float b2v = do2 ? bi2[c2] : 0.f;

    const float* __restrict__ gp = g_gi + (size_t)b * Ll * G6 + t;
    float* __restrict__ oh = outHist + (size_t)b * Ll * NS;
    float c = 0.f;
    __syncthreads();

    for (int l0 = 0; l0 < Ll; l0 += 8){
        float gv[8][6];
        #pragma unroll
        for (int s = 0; s < 8; s++){
            const float* p = gp + (size_t)(l0 + s) * G6;
            #pragma unroll
            for (int ch = 0; ch < 6; ch++) gv[s][ch] = p[ch * 64];
        }
        #pragma unroll
        for (int s = 0; s < 8; s++){
            c = gv[s][1]*c + gv[s][0]*gv[s][2];
            float cd = gv[s][5] + (c - gv[s][5]) * gv[s][4];
            h_s[s*68 + t] = gv[s][3] * tanhf(cd);
        }
        __syncthreads();

        // layer1: thread handles step s_my, columns j4, j4+8, j4+16, j4+24
        float a0=0.f, a1=0.f, a2=0.f, a3=0.f;
        #pragma unroll
        for (int q = 0; q < 16; q++){
            float4 hv = *(const float4*)&h_s[s_my*68 + 4*q];
            float4 w0 = *(const float4*)&sW1[(j4     )*68 + 4*q];
            float4 w1 = *(const float4*)&sW1[(j4 +  8)*68 + 4*q];
            float4 w2 = *(const float4*)&sW1[(j4 + 16)*68 + 4*q];
            float4 w3 = *(const float4*)&sW1[(j4 + 24)*68 + 4*q];
            a0 = fmaf(hv.x,w0.x,fmaf(hv.y,w0.y,fmaf(hv.z,w0.z,fmaf(hv.w,w0.w,a0))));
            a1 = fmaf(hv.x,w1.x,fmaf(hv.y,w1.y,fmaf(hv.z,w1.z,fmaf(hv.w,w1.w,a1))));
            a2 = fmaf(hv.x,w2.x,fmaf(hv.y,w2.y,fmaf(hv.z,w2.z,fmaf(hv.w,w2.w,a2))));
            a3 = fmaf(hv.x,w3.x,fmaf(hv.y,w3.y,fmaf(hv.z,w3.z,fmaf(hv.w,w3.w,a3))));
        }
        tt[s_my*32 + j4     ] = gelu_(a0 + b1v[0]);
        tt[s_my*32 + j4 +  8] = gelu_(a1 + b1v[1]);
        tt[s_my*32 + j4 + 16] = gelu_(a2 + b1v[2]);
        tt[s_my*32 + j4 + 24] = gelu_(a3 + b1v[3]);
        __syncthreads();

        if (do2){
            float ss = b2v;
            #pragma unroll
            for (int k = 0; k < 32; k++) ss += tt[s2*32 + k] * sW2[k*NS + c2];
            oh[(size_t)(l0 + s2) * NS + c2] = softplus_(ss);
        }
    }
    g_clast[b * Dd + t] = c;
}

// ---------------- K4 (idx 4): current gates + cell (dt=0 -> c_dec = c) ------
__global__ void gcur_cell_kernel(const float* __restrict__ Wg)
{
    __shared__ float Er[64];
    __shared__ float sc[4*64];
    int b = blockIdx.x, t = threadIdx.x;   // 256
    if (t < 64) Er[t] = g_ecur[b * Dd + t];
    __syncthreads();
    float s = g_beff[t];
    #pragma unroll 8
    for (int k = 0; k < 64; k++) s = fmaf(Er[k], Wg[(size_t)k * G6 + t], s);
    int ch = t >> 6;
    sc[t] = (ch == 2) ? tanhf(s) : sigm_(s);
    __syncthreads();
    if (t < 64){
        float cc = sc[64 + t] * g_clast[b * Dd + t] + sc[t] * sc[128 + t];
        g_hcur[b * Dd + t] = sc[192 + t] * tanhf(cc);
    }
}

// ---------------- K5 (idx 5): current intensity (4 blocks) ----------------
__global__ __launch_bounds__(256) void intensity_cur_kernel(
    const float* __restrict__ bi1,
    const float* __restrict__ Wi2, const float* __restrict__ bi2,
    float* __restrict__ out)
{
    __shared__ __align__(16) float Hs[64][68];
    __shared__ __align__(16) float W1s[2048];   // packed [16][32][4]
    __shared__ float T1s[64][33];

    const int t = threadIdx.x;
    const int r0 = blockIdx.x * 64;

    #pragma unroll
    for (int q = 0; q < 4; q++){
        int f = t + 256*q;
        int row = f >> 4, c4 = (f & 15) * 4;
        *(float4*)&Hs[row][c4] = *(const float4*)(g_hcur + (size_t)(r0 + row) * Dd + c4);
    }
    #pragma unroll
    for (int q = 0; q < 2; q++){
        int f = t + 256*q;
        ((float4*)W1s)[f] = ((const float4*)g_W1c)[f];
    }
    __syncthreads();

    const int col = t & 31;
    const int rb  = t >> 5;
    float s[8] = {0,0,0,0,0,0,0,0};
    #pragma unroll
    for (int kc = 0; kc < 16; kc++){
        float4 b = *(const float4*)&W1s[kc*128 + col*4];
        #pragma unroll
        for (int i = 0; i < 8; i++){
            float4 a = *(const float4*)&Hs[rb*8 + i][4*kc];
            s[i] = fmaf(a.x,b.x,fmaf(a.y,b.y,fmaf(a.z,b.z,fmaf(a.w,b.w,s[i]))));
        }
    }
    const float b1 = bi1[col];
    #pragma unroll
    for (int i = 0; i < 8; i++)
        T1s[rb*8 + i][col] = gelu_(s[i] + b1);
    __syncthreads();

    for (int off = t; off < 64 * NS; off += 256){
        int row = off / NS, c = off % NS;
        float ss = bi2[c];
        #pragma unroll 8
        for (int k = 0; k < 32; k++) ss += T1s[row][k] * Wi2[k * NS + c];
        out[(size_t)(r0 + row) * NS + c] = softplus_(ss);
    }
}

// ---------------- K6 (idx 6): logits + softmax + tte ----------------
__global__ void final_kernel(const float* __restrict__ Ws2, const float* __restrict__ bs2,
                             const float* __restrict__ Wq1, const float* __restrict__ bq1,
                             const float* __restrict__ Wq2, const float* __restrict__ bq2,
                             float* __restrict__ dout)
{
    __shared__ float sW2[G6 * NS];
    __shared__ float sQ1[Dd * 32];
    int b = threadIdx.x;

    for (int i = b; i < G6 * NS; i += 256) sW2[i] = Ws2[i];
    for (int i = b; i < Dd * 32; i += 256) sQ1[i] = Wq1[i];
    __syncthreads();

    float lg[NS];
    #pragma unroll
    for (int c = 0; c < NS; c++) lg[c] = bs2[c];
    #pragma unroll 4
    for (int k = 0; k < G6; k++){
        float tv = g_tdirT[(size_t)k * Bb + b];
        #pragma unroll
        for (int c = 0; c < NS; c++) lg[c] += tv * sW2[k * NS + c];
    }

    const float* ci = dout + OFF_CI + (size_t)b * NS;
    float li[NS], mx = -1e30f;
    #pragma unroll
    for (int c = 0; c < NS; c++){ li[c] = lg[c] + logf(ci[c]); mx = fmaxf(mx, li[c]); }
    float den = 0.f, ex[NS];
    #pragma unroll
    for (int c = 0; c < NS; c++){ ex[c] = expf(li[c] - mx); den += ex[c]; }
    float inv = 1.f / den;
    #pragma unroll
    for (int c = 0; c < NS; c++) dout[OFF_PROBS + (size_t)b * NS + c] = ex[c] * inv;

    float t2[32];
    #pragma unroll
    for (int c = 0; c < 32; c++) t2[c] = bq1[c];
    const float* hr = g_hcur + (size_t)b * Dd;
    #pragma unroll 4
    for (int k = 0; k < Dd; k++){
        float hv = hr[k];
        #pragma unroll
        for (int c = 0; c < 32; c++) t2[c] += hv * sQ1[k * 32 + c];
    }
    float q = bq2[0];
    #pragma unroll
    for (int c = 0; c < 32; c++) q += gelu_(t2[c]) * Wq2[c];
    dout[OFF_TTE + b] = softplus_(q);
}

// ---------------- launch ----------------
extern "C" void kernel_launch(void* const* d_in, const int* in_sizes, int n_in,
                              void* d_out, int out_size)
{
    const float* cls   = (const float*)d_in[0];
    const float* ev    = (const float*)d_in[1];
    const float* days  = (const float*)d_in[2];
    const float* We    = (const float*)d_in[3];
    const float* be    = (const float*)d_in[4];
    const float* Wtime = (const float*)d_in[5];
    const float* btime = (const float*)d_in[6];
    const float* Wg    = (const float*)d_in[7];
    const float* bg    = (const float*)d_in[8];
    const float* Wi1   = (const float*)d_in[9];
    const float* bi1   = (const float*)d_in[10];
    const float* Wi2   = (const float*)d_in[11];
    const float* bi2   = (const float*)d_in[12];
    const float* Ws1   = (const float*)d_in[13];
    const float* bs1   = (const float*)d_in[14];
    const float* Ws2   = (const float*)d_in[15];
    const float* bs2   = (const float*)d_in[16];
    const float* Wq1   = (const float*)d_in[17];
    const float* bq1   = (const float*)d_in[18];
    const float* Wq2   = (const float*)d_in[19];
    const float* bq2   = (const float*)d_in[20];
    float* dout = (float*)d_out;

    const int SMEM = 14336 * 4;   // 57344 B dynamic smem (opt-in)
    cudaFuncSetAttribute(fused_main_kernel, cudaFuncAttributeMaxDynamicSharedMemorySize, SMEM);

    prep_pack_kernel<<<1, 512>>>(Wtime, btime, Wg, bg, Wi1);             // idx 0
    ecur_kernel<<<Bb/4, 256>>>(cls, We, be);                             // idx 1
    fused_main_kernel<<<412, 256, SMEM>>>(ev, days, cls, We, be, Wg, Ws1, bs1);  // idx 2
    scan_int_kernel<<<Bb, 64>>>(Wi1, bi1, Wi2, bi2, dout + OFF_HIST);    // idx 3 (profiled)
    gcur_cell_kernel<<<Bb, 256>>>(Wg);                                   // idx 4
    intensity_cur_kernel<<<Bb/64, 256>>>(bi1, Wi2, bi2, dout + OFF_CI);  // idx 5
    final_kernel<<<1, Bb>>>(Ws2, bs2, Wq1, bq1, Wq2, bq2, dout);         // idx 6
}

// round 9
// speedup vs baseline: 2.2049x; 1.2362x over previous
#include <cuda_runtime.h>
#include <math.h>

#define Bb 256
#define Ll 200
#define Hh 768
#define Dd 64
#define Mm (Bb*Ll)          // 51200
#define G6 384
#define NS 6

#define OFF_PROBS 0
#define OFF_TTE   1536
#define OFF_CI    1792
#define OFF_HIST  3328

// ---------------- scratch (device globals; no allocation) ----------------
__device__ __align__(16) float g_gi[(size_t)Mm*G6];      // interleaved gates [row][ch*64+d]
__device__ __align__(16) float g_clast[Bb*Dd];
__device__ __align__(16) float g_ecur[Bb*Dd];
__device__ __align__(16) float g_tdir[(size_t)Bb*G6];    // row-major [b][col]
__device__ __align__(16) float g_v[G6];
__device__ __align__(16) float g_beff[G6];

// ---------------- math helpers ----------------
__device__ __forceinline__ float sigm_(float x){ return 1.f/(1.f+expf(-x)); }
__device__ __forceinline__ float softplus_(float x){
    return (x > 0.f) ? (x + log1pf(expf(-x))) : log1pf(expf(x));
}
__device__ __forceinline__ float gelu_(float x){
    return 0.5f * x * (1.f + erff(x * 0.70710678118654752440f));
}

// ---------------- K0 (idx 0): rank-1 time-feature folding ----------------
__global__ void prep_kernel(const float* __restrict__ Wtime, const float* __restrict__ btime,
                            const float* __restrict__ Wg, const float* __restrict__ bg)
{
    int j = threadIdx.x;
    if (j >= G6) return;
    float v = 0.f, bf = bg[j];
    #pragma unroll 8
    for (int d = 0; d < Dd; d++){
        float w = Wg[(size_t)(Dd + d) * G6 + j];
        v  += Wtime[d] * w;
        bf += btime[d] * w;
    }
    g_v[j] = v;
    g_beff[j] = bf;
}

// ---------------- K1 (idx 1): E_cur = cls@We + be ----------------
__global__ void ecur_kernel(const float* __restrict__ cls,
                            const float* __restrict__ We, const float* __restrict__ be)
{
    int b = blockIdx.x * 4 + (threadIdx.x >> 6);
    int d = threadIdx.x & 63;
    float s = be[d];
    const float* xr = cls + (size_t)b * Hh;
    #pragma unroll 4
    for (int k = 0; k < Hh; k += 4){
        float4 x = *(const float4*)(xr + k);
        s = fmaf(x.x, We[(size_t)(k+0)*Dd + d], s);
        s = fmaf(x.y, We[(size_t)(k+1)*Dd + d], s);
        s = fmaf(x.z, We[(size_t)(k+2)*Dd + d], s);
        s = fmaf(x.w, We[(size_t)(k+3)*Dd + d], s);
    }
    g_ecur[b * Dd + d] = s;
}

// ---------------- K2 (idx 2): fused  E = X@We ; g = E@WgE + days*v + beff ----
#define FMA4(acc0,acc1,acc2,acc3) \
    acc0 = fmaf(a.x,b0.x,fmaf(a.y,b1.x,fmaf(a.z,b2.x,fmaf(a.w,b3.x,acc0)))); \
    acc1 = fmaf(a.x,b0.y,fmaf(a.y,b1.y,fmaf(a.z,b2.y,fmaf(a.w,b3.y,acc1)))); \
    acc2 = fmaf(a.x,b0.z,fmaf(a.y,b1.z,fmaf(a.z,b2.z,fmaf(a.w,b3.z,acc2)))); \
    acc3 = fmaf(a.x,b0.w,fmaf(a.y,b1.w,fmaf(a.z,b2.w,fmaf(a.w,b3.w,acc3))));

__global__ void __launch_bounds__(256, 3) fused_main_kernel(
    const float* __restrict__ Xev, const float* __restrict__ days,
    const float* __restrict__ cls,
    const float* __restrict__ We,  const float* __restrict__ be,
    const float* __restrict__ Wg,
    const float* __restrict__ Ws1, const float* __restrict__ bs1)
{
    extern __shared__ float sm[];
    float* Xs  = sm;          // [2][128][16]  4096 floats
    float* Wts = sm + 4096;   // [2][16][64]   2048 floats
    float* CW  = sm;          // alias: [64][64] 4096 floats
    float* Es  = sm + 6144;   // [128][64]     8192 floats

    const int t  = threadIdx.x;
    const int tx = t & 15;
    const int ty = t >> 4;
    const int bx = blockIdx.x;
    const bool gp = (bx >= 400);

    const float* X; const float* W; int m0, c0, ldw;
    if (gp){ int idx = bx - 400; m0 = (idx & 1) * 128; c0 = (idx >> 1) * 64; X = cls; W = Ws1; ldw = G6; }
    else   { m0 = bx * 128; c0 = 0; X = Xev; W = We; ldw = Dd; }

    float acc[8][4];
    #pragma unroll
    for (int i=0;i<8;i++){ acc[i][0]=0.f; acc[i][1]=0.f; acc[i][2]=0.f; acc[i][3]=0.f; }

    const int arow = t >> 2,  akq = (t & 3) * 4;
    const int brow = t >> 4,  bc4 = (t & 15) * 4;

    const float* Xr0 = X + (size_t)(m0 + arow) * Hh + akq;
    const float* Xr1 = Xr0 + (size_t)64 * Hh;
    const float* Wr  = W + (size_t)brow * ldw + c0 + bc4;

    {
        float4 a0 = *(const float4*)(Xr0);
        float4 a1 = *(const float4*)(Xr1);
        float4 b  = *(const float4*)(Wr);
        *(float4*)&Xs[arow*16 + akq]      = a0;
        *(float4*)&Xs[(arow+64)*16 + akq] = a1;
        *(float4*)&Wts[brow*64 + bc4]     = b;
    }
    __syncthreads();

    const int NT = Hh / 16;   // 48 k-tiles
    for (int kt = 0; kt < NT; kt++){
        const int cur = kt & 1;
        if (kt < NT - 1){
            int k0 = 16*(kt+1);
            float4 a0 = *(const float4*)(Xr0 + k0);
            float4 a1 = *(const float4*)(Xr1 + k0);
            float4 b  = *(const float4*)(Wr + (size_t)k0 * ldw);
            float* Xn = Xs + (cur^1)*2048;
            float* Wn = Wts + (cur^1)*1024;
            *(float4*)&Xn[arow*16 + akq]      = a0;
            *(float4*)&Xn[(arow+64)*16 + akq] = a1;
            *(float4*)&Wn[brow*64 + bc4]      = b;
        }
        const float* Xc = Xs + cur*2048;
        const float* Wc = Wts + cur*1024;
        #pragma unroll
        for (int kc = 0; kc < 4; kc++){
            float4 b0 = *(const float4*)&Wc[(4*kc+0)*64 + 4*tx];
            float4 b1 = *(const float4*)&Wc[(4*kc+1)*64 + 4*tx];
            float4 b2 = *(const float4*)&Wc[(4*kc+2)*64 + 4*tx];
            float4 b3 = *(const float4*)&Wc[(4*kc+3)*64 + 4*tx];
            #pragma unroll
            for (int i = 0; i < 8; i++){
                float4 a = *(const float4*)&Xc[(ty+16*i)*16 + 4*kc];
                FMA4(acc[i][0], acc[i][1], acc[i][2], acc[i][3])
            }
        }
        __syncthreads();
    }

    if (gp){
        #pragma unroll
        for (int i = 0; i < 8; i++){
            int row = m0 + ty + 16*i;
            #pragma unroll
            for (int j = 0; j < 4; j++){
                int col = c0 + 4*tx + j;
                g_tdir[(size_t)row * G6 + col] = gelu_(acc[i][j] + bs1[col]);
            }
        }
        return;
    }

    float4 be4 = *(const float4*)(be + 4*tx);
    float dval[8], dtv[8];
    #pragma unroll
    for (int i = 0; i < 8; i++){
        float4 v = make_float4(acc[i][0]+be4.x, acc[i][1]+be4.y, acc[i][2]+be4.z, acc[i][3]+be4.w);
        *(float4*)&Es[(ty+16*i)*64 + 4*tx] = v;
        dval[i] = days[m0 + ty + 16*i];
        dtv[i]  = fmaxf(dval[i], 0.f);
    }
    __syncthreads();

    for (int gc = 0; gc < 6; gc++){
        #pragma unroll
        for (int q = 0; q < 4; q++){
            int f = t + 256*q;
            int r = f >> 4, c4 = (f & 15) * 4;
            *(float4*)&CW[r*64 + c4] = *(const float4*)(Wg + (size_t)r * G6 + gc*64 + c4);
        }
        __syncthreads();

        float vv[4], bf[4];
        #pragma unroll
        for (int j = 0; j < 4; j++){
            vv[j] = g_v[gc*64 + 4*tx + j];
            bf[j] = g_beff[gc*64 + 4*tx + j];
        }

        float r8[8][4];
        #pragma unroll
        for (int i=0;i<8;i++){ r8[i][0]=0.f; r8[i][1]=0.f; r8[i][2]=0.f; r8[i][3]=0.f; }

        #pragma unroll 4
        for (int kc = 0; kc < 16; kc++){
            float4 b0 = *(const float4*)&CW[(4*kc+0)*64 + 4*tx];
            float4 b1 = *(const float4*)&CW[(4*kc+1)*64 + 4*tx];
            float4 b2 = *(const float4*)&CW[(4*kc+2)*64 + 4*tx];
            float4 b3 = *(const float4*)&CW[(4*kc+3)*64 + 4*tx];
            #pragma unroll
            for (int i = 0; i < 8; i++){
                float4 a = *(const float4*)&Es[(ty+16*i)*64 + 4*kc];
                FMA4(r8[i][0], r8[i][1], r8[i][2], r8[i][3])
            }
        }

        #pragma unroll
        for (int i = 0; i < 8; i++){
            float gvv[4], ov[4];
            #pragma unroll
            for (int j = 0; j < 4; j++)
                gvv[j] = r8[i][j] + dval[i]*vv[j] + bf[j];
            if (gc == 2){
                #pragma unroll
                for (int j = 0; j < 4; j++) ov[j] = tanhf(gvv[j]);
            } else if (gc == 4){
                #pragma unroll
                for (int j = 0; j < 4; j++) ov[j] = expf(-softplus_(gvv[j]) * dtv[i]);
            } else if (gc == 5){
                #pragma unroll
                for (int j = 0; j < 4; j++) ov[j] = gvv[j];
            } else {
                #pragma unroll
                for (int j = 0; j < 4; j++) ov[j] = sigm_(gvv[j]);
            }
            float4 o4 = make_float4(ov[0], ov[1], ov[2], ov[3]);
            *(float4*)(g_gi + (size_t)(m0 + ty + 16*i) * G6 + gc*64 + 4*tx) = o4;
        }
        __syncthreads();
    }
}

// ---------------- K3 (idx 3, profiled): scan + fused intensity, double-buffered ----
__device__ __forceinline__ void ld_chunk(float (&gvb)[8][6], const float* __restrict__ gp, int l0)
{
    #pragma unroll
    for (int s = 0; s < 8; s++){
        const float* p = gp + (size_t)(l0 + s) * G6;
        #pragma unroll
        for (int ch = 0; ch < 6; ch++) gvb[s][ch] = p[ch * 64];
    }
}

__device__ __forceinline__ void do_chunk(
    float (&gvb)[8][6], int l0, float& c,
    float* h_s, float* tt, const float* sW1, const float* sW2,
    int t, int s_my, int j4, const float* b1v,
    bool do2, int s2, int c2, float b2v, float* __restrict__ oh)
{
    #pragma unroll
    for (int s = 0; s < 8; s++){
        c = gvb[s][1]*c + gvb[s][0]*gvb[s][2];
        float cd = gvb[s][5] + (c - gvb[s][5]) * gvb[s][4];
        h_s[s*68 + t] = gvb[s][3] * tanhf(cd);
    }
    __syncthreads();

    float a0=0.f, a1=0.f, a2=0.f, a3=0.f;
    #pragma unroll
    for (int q = 0; q < 16; q++){
        float4 hv = *(const float4*)&h_s[s_my*68 + 4*q];
        float4 w0 = *(const float4*)&sW1[(j4     )*68 + 4*q];
        float4 w1 = *(const float4*)&sW1[(j4 +  8)*68 + 4*q];
        float4 w2 = *(const float4*)&sW1[(j4 + 16)*68 + 4*q];
        float4 w3 = *(const float4*)&sW1[(j4 + 24)*68 + 4*q];
        a0 = fmaf(hv.x,w0.x,fmaf(hv.y,w0.y,fmaf(hv.z,w0.z,fmaf(hv.w,w0.w,a0))));
        a1 = fmaf(hv.x,w1.x,fmaf(hv.y,w1.y,fmaf(hv.z,w1.z,fmaf(hv.w,w1.w,a1))));
        a2 = fmaf(hv.x,w2.x,fmaf(hv.y,w2.y,fmaf(hv.z,w2.z,fmaf(hv.w,w2.w,a2))));
        a3 = fmaf(hv.x,w3.x,fmaf(hv.y,w3.y,fmaf(hv.z,w3.z,fmaf(hv.w,w3.w,a3))));
    }
    tt[s_my*32 + j4     ] = gelu_(a0 + b1v[0]);
    tt[s_my*32 + j4 +  8] = gelu_(a1 + b1v[1]);
    tt[s_my*32 + j4 + 16] = gelu_(a2 + b1v[2]);
    tt[s_my*32 + j4 + 24] = gelu_(a3 + b1v[3]);
    __syncthreads();

    if (do2){
        float ss = b2v;
        #pragma unroll
        for (int k = 0; k < 32; k++) ss += tt[s2*32 + k] * sW2[k*NS + c2];
        oh[(size_t)(l0 + s2) * NS + c2] = softplus_(ss);
    }
}

__global__ void __launch_bounds__(64) scan_int_kernel(
    const float* __restrict__ Wi1, const float* __restrict__ bi1,
    const float* __restrict__ Wi2, const float* __restrict__ bi2,
    float* __restrict__ outHist)
{
    __shared__ __align__(16) float sW1[32*68];   // [col][k], stride 68
    __shared__ float sW2[32*NS];
    __shared__ __align__(16) float h_s[8*68];    // [step][d], stride 68
    __shared__ float tt[8*32];                   // [step][col]

    const int b = blockIdx.x;
    const int t = threadIdx.x;   // 0..63

    for (int u = t; u < 2048; u += 64){ int k = u >> 5, j = u & 31; sW1[j*68 + k] = Wi1[u]; }
    for (int u = t; u < 32*NS; u += 64) sW2[u] = Wi2[u];

    const int s_my = t >> 3, j4 = t & 7;
    float b1v[4];
    #pragma unroll
    for (int m = 0; m < 4; m++) b1v[m] = bi1[j4 + 8*m];
    const bool do2 = (t >= 16);
    const int s2 = (t - 16) / NS, c2 = (t - 16) % NS;
    const float b2v = do2 ? bi2[c2] : 0.f;

    const float* __restrict__ gp = g_gi + (size_t)b * Ll * G6 + t;
    float* __restrict__ oh = outHist + (size_t)b * Ll * NS;
    float c = 0.f;

    float gA[8][6], gB[8][6];
    ld_chunk(gA, gp, 0);
    __syncthreads();

    // 25 chunks: 12 pairs + tail
    for (int p = 0; p < 12; p++){
        int l0 = p * 16;
        ld_chunk(gB, gp, l0 + 8);
        do_chunk(gA, l0, c, h_s, tt, sW1, sW2, t, s_my, j4, b1v, do2, s2, c2, b2v, oh);
        ld_chunk(gA, gp, l0 + 16);
        do_chunk(gB, l0 + 8, c, h_s, tt, sW1, sW2, t, s_my, j4, b1v, do2, s2, c2, b2v, oh);
    }
    do_chunk(gA, 192, c, h_s, tt, sW1, sW2, t, s_my, j4, b1v, do2, s2, c2, b2v, oh);

    g_clast[b * Dd + t] = c;
}

// ---------------- K4 (idx 4): per-batch finish (gates+cell+intensity+tte+logits) ----
__global__ void __launch_bounds__(256) finish_kernel(
    const float* __restrict__ Wg,
    const float* __restrict__ Wi1, const float* __restrict__ bi1,
    const float* __restrict__ Wi2, const float* __restrict__ bi2,
    const float* __restrict__ Ws2, const float* __restrict__ bs2,
    const float* __restrict__ Wq1, const float* __restrict__ bq1,
    const float* __restrict__ Wq2, const float* __restrict__ bq2,
    float* __restrict__ dout)
{
    __shared__ float Er[64], sc[256], hb[64], t1[32], tq[32], ci[NS], lgs[NS];
    const int b = blockIdx.x, t = threadIdx.x;
    const int lane = t & 31, w = t >> 5;

    if (t < 64) Er[t] = g_ecur[b * Dd + t];
    __syncthreads();

    // gates: 256 cols (4 channels x 64), dt=0 path
    {
        float s = g_beff[t];
        #pragma unroll 8
        for (int k = 0; k < 64; k++) s = fmaf(Er[k], Wg[(size_t)k * G6 + t], s);
        sc[t] = ((t >> 6) == 2) ? tanhf(s) : sigm_(s);
    }
    __syncthreads();

    if (t < 64){
        float cc = sc[64 + t] * g_clast[b * Dd + t] + sc[t] * sc[128 + t];
        hb[t] = sc[192 + t] * tanhf(cc);
    }
    if (w >= 2){            // logits col c = w-2 (6 warps), coalesced over k
        int cc = w - 2;
        const float* tr = g_tdir + (size_t)b * G6;
        float p = 0.f;
        #pragma unroll
        for (int m = 0; m < 12; m++){
            int k = lane + 32*m;
            p = fmaf(tr[k], Ws2[(size_t)k * NS + cc], p);
        }
        #pragma unroll
        for (int off = 16; off > 0; off >>= 1) p += __shfl_xor_sync(0xffffffff, p, off);
        if (lane == 0) lgs[cc] = p + bs2[cc];
    }
    __syncthreads();

    if (t < 32){            // intensity L1 + tte L1 together
        float s1 = bi1[t], sq = bq1[t];
        #pragma unroll 8
        for (int k = 0; k < 64; k++){
            float hv = hb[k];
            s1 = fmaf(hv, Wi1[(size_t)k * 32 + t], s1);
            sq = fmaf(hv, Wq1[(size_t)k * 32 + t], sq);
        }
        t1[t] = gelu_(s1);
        tq[t] = gelu_(sq);
    }
    __syncthreads();

    if (w == 0){            // tte reduce
        float p = tq[lane] * Wq2[lane];
        #pragma unroll
        for (int off = 16; off > 0; off >>= 1) p += __shfl_xor_sync(0xffffffff, p, off);
        if (lane == 0) dout[OFF_TTE + b] = softplus_(p + bq2[0]);
    }
    if (w == 1 && lane < NS){   // intensity L2
        float ss = bi2[lane];
        #pragma unroll
        for (int k = 0; k < 32; k++) ss += t1[k] * Wi2[k * NS + lane];
        float v = softplus_(ss);
        ci[lane] = v;
        dout[OFF_CI + (size_t)b * NS + lane] = v;
    }
    __syncthreads();

    if (t == 0){            // softmax over 6
        float li[NS], mx = -1e30f;
        #pragma unroll
        for (int c = 0; c < NS; c++){ li[c] = lgs[c] + logf(ci[c]); mx = fmaxf(mx, li[c]); }
        float den = 0.f, ex[NS];
        #pragma unroll
        for (int c = 0; c < NS; c++){ ex[c] = expf(li[c] - mx); den += ex[c]; }
        float inv = 1.f / den;
        #pragma unroll
        for (int c = 0; c < NS; c++) dout[OFF_PROBS + (size_t)b * NS + c] = ex[c] * inv;
    }
}

// ---------------- launch ----------------
extern "C" void kernel_launch(void* const* d_in, const int* in_sizes, int n_in,
                              void* d_out, int out_size)
{
    const float* cls   = (const float*)d_in[0];
    const float* ev    = (const float*)d_in[1];
    const float* days  = (const float*)d_in[2];
    const float* We    = (const float*)d_in[3];
    const float* be    = (const float*)d_in[4];
    const float* Wtime = (const float*)d_in[5];
    const float* btime = (const float*)d_in[6];
    const float* Wg    = (const float*)d_in[7];
    const float* bg    = (const float*)d_in[8];
    const float* Wi1   = (const float*)d_in[9];
    const float* bi1   = (const float*)d_in[10];
    const float* Wi2   = (const float*)d_in[11];
    const float* bi2   = (const float*)d_in[12];
    const float* Ws1   = (const float*)d_in[13];
    const float* bs1   = (const float*)d_in[14];
    const float* Ws2   = (const float*)d_in[15];
    const float* bs2   = (const float*)d_in[16];
    const float* Wq1   = (const float*)d_in[17];
    const float* bq1   = (const float*)d_in[18];
    const float* Wq2   = (const float*)d_in[19];
    const float* bq2   = (const float*)d_in[20];
    float* dout = (float*)d_out;

    const int SMEM = 14336 * 4;   // 57344 B dynamic smem (opt-in)
    cudaFuncSetAttribute(fused_main_kernel, cudaFuncAttributeMaxDynamicSharedMemorySize, SMEM);

    prep_kernel<<<1, G6>>>(Wtime, btime, Wg, bg);                         // idx 0
    ecur_kernel<<<Bb/4, 256>>>(cls, We, be);                              // idx 1
    fused_main_kernel<<<412, 256, SMEM>>>(ev, days, cls, We, be, Wg, Ws1, bs1);  // idx 2
    scan_int_kernel<<<Bb, 64>>>(Wi1, bi1, Wi2, bi2, dout + OFF_HIST);     // idx 3 (profiled)
    finish_kernel<<<Bb, 256>>>(Wg, Wi1, bi1, Wi2, bi2, Ws2, bs2,
                               Wq1, bq1, Wq2, bq2, dout);                 // idx 4
}